// round 14
// baseline (speedup 1.0000x reference)
#include <cuda_runtime.h>
#include <math.h>

// Problem constants (fixed shapes for this problem instance)
#define N_NODES 100000
#define N_EDGES 1600000
#define HF 128
#define TOT_E (N_EDGES + N_NODES)   // edges + self loops
#define NH (N_NODES * HF)
#define EPS 1e-5f
#define NSTATS 18
#define BM 128
#define BK 16

// ---------------- static device scratch (allocation-free rule) ----------------
__device__ __align__(16) float d_xs[9][NH];  // skip stack (RAW agg outputs)
__device__ __align__(16) float d_tmp[NH];    // GEMM output / agg input
__device__ __align__(16) float d_hA[NH];     // RAW agg outputs (ping/pong)
__device__ __align__(16) float d_hB[NH];
__device__ int   d_deg[N_NODES];
__device__ float d_dinv[N_NODES];
__device__ int   d_offs[N_NODES + 1];
__device__ int   d_cursor[N_NODES];
__device__ __align__(16) int2 d_csr2[TOT_E]; // (src, norm-bits) per CSR slot
__device__ int   d_part[256];                // scan partials
__device__ __align__(16) float d_sums[NSTATS][HF];
__device__ __align__(16) float d_sqs[NSTATS][HF];
__device__ __align__(16) float d_bnsc[NSTATS][HF];  // precomputed BN scale
__device__ __align__(16) float d_bnsh[NSTATS][HF];  // precomputed BN shift
__device__ float d_t1[N_NODES];              // last-layer scalar pre-aggregation
__device__ int   d_stride;                   // 1: edge_index int32, 2: int64
__device__ int   d_ticket[NSTATS];           // agg last-block tickets
__device__ unsigned d_barc;                  // global barrier counter (monotonic)

// Buffer selector: 0..8 -> xs[k], 9 -> hA, 10 -> hB (device-side only).
__device__ __forceinline__ float* sel_buf(int k) {
    if (k < 9)   return d_xs[k];
    if (k == 9)  return d_hA;
    return d_hB;
}

// packed fp32x2 fma (sm_100+): d = a*b + d on two lanes at once
__device__ __forceinline__ void fma2(unsigned long long& d,
                                     unsigned long long a, unsigned long long b) {
    asm("fma.rn.f32x2 %0, %1, %2, %0;" : "+l"(d) : "l"(a), "l"(b));
}
__device__ __forceinline__ unsigned long long splat2(float f) {
    unsigned long long p;
    unsigned int u = __float_as_uint(f);
    asm("mov.b64 %0, {%1, %1};" : "=l"(p) : "r"(u));
    return p;
}

// ---------------- global barrier (replay-safe: monotonic counter) ----------------
__device__ __forceinline__ void gbar() {
    __syncthreads();
    if (threadIdx.x == 0) {
        __threadfence();
        unsigned nb = gridDim.x;
        unsigned t = atomicAdd(&d_barc, 1u) + 1u;
        unsigned target = ((t + nb - 1u) / nb) * nb;
        while (*((volatile unsigned*)&d_barc) < target) {}
    }
    __syncthreads();
}

__device__ __forceinline__ int edge_src(const int* ei, int E, int e) {
    return (d_stride == 2) ? ei[2 * e] : ei[e];
}
__device__ __forceinline__ int edge_dst(const int* ei, int E, int e) {
    return (d_stride == 2) ? ei[2 * (E + e)] : ei[E + e];
}

// ---------------- one-shot graph build (persistent, 128 co-resident blocks) ----
__global__ void __launch_bounds__(512, 1)
build_k(const int* __restrict__ ei, int E, int n) {
    __shared__ int sm[512];
    const int G = gridDim.x, Tn = blockDim.x;
    const int NT = G * Tn;
    const int gtid = blockIdx.x * Tn + threadIdx.x;
    const int chunk = (n + G - 1) / G;

    // P0: init deg (self loop), zero stats + tickets, detect edge dtype
    for (int i = gtid; i < n; i += NT) d_deg[i] = 1;
    for (int i = gtid; i < NSTATS * HF; i += NT) {
        ((float*)d_sums)[i] = 0.f;
        ((float*)d_sqs)[i] = 0.f;
    }
    for (int i = gtid; i < NSTATS; i += NT) d_ticket[i] = 0;
    if (blockIdx.x == 0 && threadIdx.x < 32) {
        // int64 little-endian with values < 2^31 -> odd words all zero
        long long total = 2LL * E;
        long long step = total / 33;
        long long pos = ((long long)(threadIdx.x + 1) * step) | 1;
        if (pos >= total) pos = 1;
        unsigned nz = __ballot_sync(0xffffffffu, ei[pos] != 0);
        if (threadIdx.x == 0) d_stride = (nz == 0u) ? 2 : 1;
    }
    gbar();

    // P1: degree count
    for (int e = gtid; e < E; e += NT) atomicAdd(&d_deg[edge_dst(ei, E, e)], 1);
    gbar();

    // P2: dinv
    for (int i = gtid; i < n; i += NT) d_dinv[i] = rsqrtf((float)d_deg[i]);
    gbar();

    // P3: block-local exclusive scan over this block's node chunk
    {
        int cs = blockIdx.x * chunk;
        int ce = min(cs + chunk, n);
        int base = cs + threadIdx.x * 4;
        int vals[4];
        int lsum = 0;
#pragma unroll
        for (int j = 0; j < 4; j++) {
            int idx = base + j;
            int dv = (idx < ce) ? d_deg[idx] : 0;
            vals[j] = dv; lsum += dv;
        }
        sm[threadIdx.x] = lsum;
        __syncthreads();
        for (int d = 1; d < 512; d <<= 1) {
            int t = (threadIdx.x >= d) ? sm[threadIdx.x - d] : 0;
            __syncthreads();
            sm[threadIdx.x] += t;
            __syncthreads();
        }
        int run = sm[threadIdx.x] - lsum;
#pragma unroll
        for (int j = 0; j < 4; j++) {
            int idx = base + j;
            if (idx < ce) { d_offs[idx] = run; run += vals[j]; }
        }
        if (threadIdx.x == Tn - 1) d_part[blockIdx.x] = sm[Tn - 1];
    }
    gbar();

    // P4: block 0 scans the per-block partials (exclusive)
    if (blockIdx.x == 0) {
        int t = threadIdx.x;
        int v = (t < G) ? d_part[t] : 0;
        sm[t] = v;
        __syncthreads();
        for (int d = 1; d < 512; d <<= 1) {
            int u = (t >= d) ? sm[t - d] : 0;
            __syncthreads();
            sm[t] += u;
            __syncthreads();
        }
        if (t < G) d_part[t] = sm[t] - v;
    }
    gbar();

    // P5: finalize offsets, self-loop entries, cursors
    for (int i = gtid; i < n; i += NT) {
        int off = d_offs[i] + d_part[i / chunk];
        d_offs[i] = off;
        float dv = d_dinv[i];
        d_csr2[off] = make_int2(i, __float_as_int(dv * dv));
        d_cursor[i] = off + 1;
    }
    if (gtid == 0) d_offs[n] = n + E;
    gbar();

    // P6: scatter edges
    for (int e = gtid; e < E; e += NT) {
        int s = edge_src(ei, E, e);
        int d = edge_dst(ei, E, e);
        int p = atomicAdd(&d_cursor[d], 1);
        d_csr2[p] = make_int2(s, __float_as_int(d_dinv[s] * d_dinv[d]));
    }
}

// ---------------- per-layer kernels ----------------
// first layer: d_tmp = x[N,3] @ W0[3,128]   (raw input, no BN)
__global__ void gemm3_k(const float* __restrict__ x, const float* __restrict__ W0,
                        int n) {
    int i = blockIdx.x * blockDim.x + threadIdx.x;
    if (i >= n * 32) return;
    int v = i >> 5;
    int c = (i & 31) << 2;
    float x0 = x[v * 3 + 0], x1 = x[v * 3 + 1], x2 = x[v * 3 + 2];
    float4 w0 = *(const float4*)&W0[c];
    float4 w1 = *(const float4*)&W0[HF + c];
    float4 w2 = *(const float4*)&W0[2 * HF + c];
    float4 o;
    o.x = x0 * w0.x + x1 * w1.x + x2 * w2.x;
    o.y = x0 * w0.y + x1 * w1.y + x2 * w2.y;
    o.z = x0 * w0.z + x1 * w1.z + x2 * w2.z;
    o.w = x0 * w0.w + x1 * w1.w + x2 * w2.w;
    *(float4*)&d_tmp[v * HF + c] = o;
}

// d_tmp[N,128] = (relu(bn_a(A)) [+ relu(bn_b(B))]) @ W[128,128]
// 128x128x16 tile, 256 threads, 8x8 microtile, f32x2 FMA, double-buffered smem.
__global__ void __launch_bounds__(256, 2)
gemm128_k(int aSel, int aStat, int bSel, int bStat,
          const float* __restrict__ W, int n) {
    __shared__ __align__(16) float As[2][BM][20];   // 80B row stride
    __shared__ __align__(16) float Ws[2][BK][HF];
    __shared__ __align__(16) float scA[HF], shA[HF], scB[HF], shB[HF];
    const float* A = sel_buf(aSel);
    const float* B = (bSel >= 0) ? sel_buf(bSel) : (const float*)0;
    int tid = threadIdx.x;
    if (tid < HF) {
        scA[tid] = d_bnsc[aStat][tid];
        shA[tid] = d_bnsh[aStat][tid];
        if (bSel >= 0) { scB[tid] = d_bnsc[bStat][tid]; shB[tid] = d_bnsh[bStat][tid]; }
    }
    int brow = blockIdx.x * BM;
    int r0 = (tid >> 4) << 3;      // 0..120 step 8
    int c0 = (tid & 15) << 3;      // 0..120 step 8
    __syncthreads();   // BN consts visible

    float4 pa[2], pw[2];
    // prefetch chunk k0=0
#pragma unroll
    for (int i = 0; i < 2; i++) {
        int idx = tid + i * 256;
        int ar = idx >> 2, ac = (idx & 3) << 2;
        int grow = brow + ar, f = ac;
        float4 v = make_float4(0.f, 0.f, 0.f, 0.f);
        if (grow < n) {
            float4 a4 = *(const float4*)&A[(size_t)grow * HF + f];
            float4 sa = *(float4*)&scA[f];
            float4 ha = *(float4*)&shA[f];
            v.x = fmaxf(fmaf(a4.x, sa.x, ha.x), 0.f);
            v.y = fmaxf(fmaf(a4.y, sa.y, ha.y), 0.f);
            v.z = fmaxf(fmaf(a4.z, sa.z, ha.z), 0.f);
            v.w = fmaxf(fmaf(a4.w, sa.w, ha.w), 0.f);
            if (B) {
                float4 b4 = *(const float4*)&B[(size_t)grow * HF + f];
                float4 sb = *(float4*)&scB[f];
                float4 hb = *(float4*)&shB[f];
                v.x += fmaxf(fmaf(b4.x, sb.x, hb.x), 0.f);
                v.y += fmaxf(fmaf(b4.y, sb.y, hb.y), 0.f);
                v.z += fmaxf(fmaf(b4.z, sb.z, hb.z), 0.f);
                v.w += fmaxf(fmaf(b4.w, sb.w, hb.w), 0.f);
            }
        }
        pa[i] = v;
        int kr = idx >> 5, cc = (idx & 31) << 2;
        pw[i] = *(const float4*)&W[(size_t)kr * HF + cc];
    }
    // store stage 0
#pragma unroll
    for (int i = 0; i < 2; i++) {
        int idx = tid + i * 256;
        *(float4*)&As[0][idx >> 2][(idx & 3) << 2] = pa[i];
        *(float4*)&Ws[0][idx >> 5][(idx & 31) << 2] = pw[i];
    }
    __syncthreads();

    unsigned long long acc[8][4];
#pragma unroll
    for (int r = 0; r < 8; r++)
#pragma unroll
        for (int j = 0; j < 4; j++) acc[r][j] = 0ULL;

    int buf = 0;
    for (int k0 = 0; k0 < HF; k0 += BK) {
        int nk = k0 + BK;
        if (nk < HF) {
            // prefetch next chunk into regs
#pragma unroll
            for (int i = 0; i < 2; i++) {
                int idx = tid + i * 256;
                int ar = idx >> 2, ac = (idx & 3) << 2;
                int grow = brow + ar, f = nk + ac;
                float4 v = make_float4(0.f, 0.f, 0.f, 0.f);
                if (grow < n) {
                    float4 a4 = *(const float4*)&A[(size_t)grow * HF + f];
                    float4 sa = *(float4*)&scA[f];
                    float4 ha = *(float4*)&shA[f];
                    v.x = fmaxf(fmaf(a4.x, sa.x, ha.x), 0.f);
                    v.y = fmaxf(fmaf(a4.y, sa.y, ha.y), 0.f);
                    v.z = fmaxf(fmaf(a4.z, sa.z, ha.z), 0.f);
                    v.w = fmaxf(fmaf(a4.w, sa.w, ha.w), 0.f);
                    if (B) {
                        float4 b4 = *(const float4*)&B[(size_t)grow * HF + f];
                        float4 sb = *(float4*)&scB[f];
                        float4 hb = *(float4*)&shB[f];
                        v.x += fmaxf(fmaf(b4.x, sb.x, hb.x), 0.f);
                        v.y += fmaxf(fmaf(b4.y, sb.y, hb.y), 0.f);
                        v.z += fmaxf(fmaf(b4.z, sb.z, hb.z), 0.f);
                        v.w += fmaxf(fmaf(b4.w, sb.w, hb.w), 0.f);
                    }
                }
                pa[i] = v;
                int kr = idx >> 5, cc = (idx & 31) << 2;
                pw[i] = *(const float4*)&W[(size_t)(nk + kr) * HF + cc];
            }
        }
        // compute on current buffer
#pragma unroll
        for (int kk = 0; kk < BK; kk++) {
            ulonglong2 t0 = *(ulonglong2*)&Ws[buf][kk][c0];
            ulonglong2 t1 = *(ulonglong2*)&Ws[buf][kk][c0 + 4];
            unsigned long long bp0 = t0.x, bp1 = t0.y, bp2 = t1.x, bp3 = t1.y;
#pragma unroll
            for (int r = 0; r < 8; r++) {
                unsigned long long ap = splat2(As[buf][r0 + r][kk]);
                fma2(acc[r][0], ap, bp0);
                fma2(acc[r][1], ap, bp1);
                fma2(acc[r][2], ap, bp2);
                fma2(acc[r][3], ap, bp3);
            }
        }
        if (nk < HF) {
#pragma unroll
            for (int i = 0; i < 2; i++) {
                int idx = tid + i * 256;
                *(float4*)&As[buf ^ 1][idx >> 2][(idx & 3) << 2] = pa[i];
                *(float4*)&Ws[buf ^ 1][idx >> 5][(idx & 31) << 2] = pw[i];
            }
        }
        __syncthreads();
        buf ^= 1;
    }
#pragma unroll
    for (int r = 0; r < 8; r++) {
        int grow = brow + r0 + r;
        if (grow < n) {
            *(ulonglong2*)&d_tmp[(size_t)grow * HF + c0] =
                make_ulonglong2(acc[r][0], acc[r][1]);
            *(ulonglong2*)&d_tmp[(size_t)grow * HF + c0 + 4] =
                make_ulonglong2(acc[r][2], acc[r][3]);
        }
    }
}

// aggregation: sel(dstSel)[v] = sum_{csr} norm * d_tmp[src]; warp/node.
// Fused BN stats + last-block BN-param finalize (ticket).
__global__ void __launch_bounds__(256, 4)
agg128_k(int n, int dstSel, int statIdx,
         const float* __restrict__ g, const float* __restrict__ b, float invN) {
    float* dst = sel_buf(dstSel);
    const float4* T = (const float4*)d_tmp;
    int gw = (blockIdx.x * blockDim.x + threadIdx.x) >> 5;
    int lane = threadIdx.x & 31;
    int nwarps = (gridDim.x * blockDim.x) >> 5;
    float4 ssum = make_float4(0.f, 0.f, 0.f, 0.f);
    float4 ssq  = make_float4(0.f, 0.f, 0.f, 0.f);
    for (int v = gw; v < n; v += nwarps) {
        int bo = d_offs[v], e = d_offs[v + 1];
        float4 acc = make_float4(0.f, 0.f, 0.f, 0.f);
        int i = bo;
        for (; i + 4 <= e; i += 4) {
            int2 c0 = d_csr2[i],     c1 = d_csr2[i + 1];
            int2 c2 = d_csr2[i + 2], c3 = d_csr2[i + 3];
            float4 v0 = __ldg(&T[(size_t)c0.x * 32 + lane]);
            float4 v1 = __ldg(&T[(size_t)c1.x * 32 + lane]);
            float4 v2 = __ldg(&T[(size_t)c2.x * 32 + lane]);
            float4 v3 = __ldg(&T[(size_t)c3.x * 32 + lane]);
            float n0 = __int_as_float(c0.y), n1 = __int_as_float(c1.y);
            float n2 = __int_as_float(c2.y), n3 = __int_as_float(c3.y);
            acc.x += n0 * v0.x + n1 * v1.x + n2 * v2.x + n3 * v3.x;
            acc.y += n0 * v0.y + n1 * v1.y + n2 * v2.y + n3 * v3.y;
            acc.z += n0 * v0.z + n1 * v1.z + n2 * v2.z + n3 * v3.z;
            acc.w += n0 * v0.w + n1 * v1.w + n2 * v2.w + n3 * v3.w;
        }
        for (; i < e; i++) {
            int2 c = d_csr2[i];
            float4 v0 = __ldg(&T[(size_t)c.x * 32 + lane]);
            float nn = __int_as_float(c.y);
            acc.x += nn * v0.x; acc.y += nn * v0.y;
            acc.z += nn * v0.z; acc.w += nn * v0.w;
        }
        *(float4*)&dst[(size_t)v * HF + lane * 4] = acc;
        ssum.x += acc.x; ssum.y += acc.y; ssum.z += acc.z; ssum.w += acc.w;
        ssq.x += acc.x * acc.x; ssq.y += acc.y * acc.y;
        ssq.z += acc.z * acc.z; ssq.w += acc.w * acc.w;
    }
    int f = lane * 4;
    atomicAdd(&d_sums[statIdx][f + 0], ssum.x);
    atomicAdd(&d_sums[statIdx][f + 1], ssum.y);
    atomicAdd(&d_sums[statIdx][f + 2], ssum.z);
    atomicAdd(&d_sums[statIdx][f + 3], ssum.w);
    atomicAdd(&d_sqs[statIdx][f + 0], ssq.x);
    atomicAdd(&d_sqs[statIdx][f + 1], ssq.y);
    atomicAdd(&d_sqs[statIdx][f + 2], ssq.z);
    atomicAdd(&d_sqs[statIdx][f + 3], ssq.w);

    // last-block BN param finalize
    __shared__ int is_last;
    __threadfence();
    if (threadIdx.x == 0) {
        int t = atomicAdd(&d_ticket[statIdx], 1);
        is_last = (t == (int)gridDim.x - 1);
    }
    __syncthreads();
    if (is_last && threadIdx.x < HF) {
        int t0 = threadIdx.x;
        float s_ = *((volatile float*)&d_sums[statIdx][t0]);
        float q_ = *((volatile float*)&d_sqs[statIdx][t0]);
        float m = s_ * invN;
        float v = q_ * invN - m * m;
        float sc = rsqrtf(v + EPS) * g[t0];
        d_bnsc[statIdx][t0] = sc;
        d_bnsh[statIdx][t0] = b[t0] - m * sc;
    }
}

// last layer: t1[v] = dot(relu(bn_h(h[v])) + relu(bn_0(xs0[v])), Wout)
__global__ void dot_out_k(int hSel, int hStat, const float* __restrict__ Wv, int n) {
    int w = (blockIdx.x * blockDim.x + threadIdx.x) >> 5;
    int lane = threadIdx.x & 31;
    if (w >= n) return;
    const float* h = sel_buf(hSel);
    int f = lane * 4;
    float4 a  = *(const float4*)&h[(size_t)w * HF + f];
    float4 b  = *(const float4*)&d_xs[0][(size_t)w * HF + f];
    float4 sh_ = *(float4*)&d_bnsc[hStat][f];
    float4 hh  = *(float4*)&d_bnsh[hStat][f];
    float4 s0  = *(float4*)&d_bnsc[0][f];
    float4 h0  = *(float4*)&d_bnsh[0][f];
    float4 ww = *(const float4*)&Wv[f];
    float sx = fmaxf(fmaf(a.x, sh_.x, hh.x), 0.f) + fmaxf(fmaf(b.x, s0.x, h0.x), 0.f);
    float sy = fmaxf(fmaf(a.y, sh_.y, hh.y), 0.f) + fmaxf(fmaf(b.y, s0.y, h0.y), 0.f);
    float sz = fmaxf(fmaf(a.z, sh_.z, hh.z), 0.f) + fmaxf(fmaf(b.z, s0.z, h0.z), 0.f);
    float sw = fmaxf(fmaf(a.w, sh_.w, hh.w), 0.f) + fmaxf(fmaf(b.w, s0.w, h0.w), 0.f);
    float s = sx * ww.x + sy * ww.y + sz * ww.z + sw * ww.w;
#pragma unroll
    for (int o = 16; o; o >>= 1) s += __shfl_down_sync(0xffffffffu, s, o);
    if (lane == 0) d_t1[w] = s;
}

__global__ void agg_sig_k(float* __restrict__ out, int n) {
    int v = blockIdx.x * blockDim.x + threadIdx.x;
    if (v >= n) return;
    int b = d_offs[v], e = d_offs[v + 1];
    float s = 0.f;
    for (int i = b; i < e; i++)
        s += __int_as_float(d_csr2[i].y) * d_t1[d_csr2[i].x];
    out[v] = 1.0f / (1.0f + expf(-s));
}

// ---------------- launcher (kernel launches ONLY — graph-capture safe) ----------------
extern "C" void kernel_launch(void* const* d_in, const int* in_sizes, int n_in,
                              void* d_out, int out_size) {
    const float* x    = (const float*)d_in[0];
    const int*   ei   = (const int*)d_in[1];     // int32 or int64, device-detected
    const float* W0   = (const float*)d_in[2];
    const float* Ws1  = (const float*)d_in[3];
    const float* g1   = (const float*)d_in[4];
    const float* b1   = (const float*)d_in[5];
    const float* Ws2  = (const float*)d_in[6];
    const float* g2   = (const float*)d_in[7];
    const float* b2   = (const float*)d_in[8];
    const float* Wout = (const float*)d_in[9];
    float* out = (float*)d_out;

    const int N = in_sizes[0] / 3;
    const int E = in_sizes[1] / 2;

    const float invN = 1.0f / (float)N;
    const int TB = 256;
    const int gN    = (N + TB - 1) / TB;
    const int g32   = (N * 32 + TB - 1) / TB;
    const int gGemm = (N + BM - 1) / BM;

    // --- graph preprocessing: one persistent kernel (software grid barrier) ---
    build_k<<<128, 512>>>(ei, E, N);

    // --- layer 0: conv1[0] -> raw agg in xs[0], stat 0 ---
    gemm3_k<<<g32, TB>>>(x, W0, N);
    agg128_k<<<2048, TB>>>(N, 0, 0, g1, b1, invN);
    int cur = 0, curStat = 0;

    // --- up phase: i = 1..9 ---
    for (int i = 1; i <= 9; i++) {
        gemm128_k<<<gGemm, TB>>>(cur, curStat, -1, 0,
                                 Ws1 + (size_t)(i - 1) * HF * HF, N);
        int dst = (i < 9) ? i : 9;               // xs[i] or hA
        agg128_k<<<2048, TB>>>(N, dst, i, g1 + (size_t)i * HF, b1 + (size_t)i * HF,
                               invN);
        cur = dst; curStat = i;
    }

    // --- down phase: i = 0..7 (skip-add + both BN+ReLU fused into GEMM) ---
    int h = 9, hStat = 9;
    for (int i = 0; i < 8; i++) {
        int j = 8 - i;                           // xs[j], stat j
        gemm128_k<<<gGemm, TB>>>(h, hStat, j, j,
                                 Ws2 + (size_t)i * HF * HF, N);
        int nh = (h == 9) ? 10 : 9;
        int st = 10 + i;
        agg128_k<<<2048, TB>>>(N, nh, st, g2 + (size_t)i * HF, b2 + (size_t)i * HF,
                               invN);
        h = nh; hStat = st;
    }

    // --- final: out = sigmoid(conv(bnrelu(h) + bnrelu(xs0), Wout)) ---
    dot_out_k<<<g32, TB>>>(h, hStat, Wout, N);
    agg_sig_k<<<gN, TB>>>(out, N);
}

// round 15
// speedup vs baseline: 1.2283x; 1.2283x over previous
#include <cuda_runtime.h>
#include <math.h>

// Problem constants (fixed shapes for this problem instance)
#define N_NODES 100000
#define N_EDGES 1600000
#define HF 128
#define TOT_E (N_EDGES + N_NODES)   // edges + self loops
#define NH (N_NODES * HF)
#define EPS 1e-5f
#define NSTATS 18
#define BM 64
#define BK 32

// ---------------- static device scratch (allocation-free rule) ----------------
__device__ __align__(16) float d_xs[9][NH];  // skip stack (RAW agg outputs)
__device__ __align__(16) float d_tmp[NH];    // GEMM output / agg input
__device__ __align__(16) float d_hA[NH];     // RAW agg outputs (ping/pong)
__device__ __align__(16) float d_hB[NH];
__device__ int   d_deg[N_NODES];
__device__ float d_dinv[N_NODES];
__device__ int   d_offs[N_NODES + 1];
__device__ int   d_cursor[N_NODES];
__device__ __align__(16) int2 d_csr2[TOT_E]; // (src, norm-bits) per CSR slot
__device__ int   d_part[256];                // scan partials
__device__ __align__(16) float d_sums[NSTATS][HF];
__device__ __align__(16) float d_sqs[NSTATS][HF];
__device__ __align__(16) float d_bnsc[NSTATS][HF];  // precomputed BN scale
__device__ __align__(16) float d_bnsh[NSTATS][HF];  // precomputed BN shift
__device__ float d_t1[N_NODES];              // last-layer scalar pre-aggregation
__device__ int   d_stride;                   // 1: edge_index int32, 2: int64
__device__ int   d_ticket[NSTATS];           // agg last-block tickets
__device__ unsigned d_barc;                  // global barrier counter (monotonic)

// Buffer selector: 0..8 -> xs[k], 9 -> hA, 10 -> hB (device-side only).
__device__ __forceinline__ float* sel_buf(int k) {
    if (k < 9)   return d_xs[k];
    if (k == 9)  return d_hA;
    return d_hB;
}

// packed fp32x2 fma (sm_100+): d = a*b + d on two lanes at once
__device__ __forceinline__ void fma2(unsigned long long& d,
                                     unsigned long long a, unsigned long long b) {
    asm("fma.rn.f32x2 %0, %1, %2, %0;" : "+l"(d) : "l"(a), "l"(b));
}
__device__ __forceinline__ unsigned long long splat2(float f) {
    unsigned long long p;
    unsigned int u = __float_as_uint(f);
    asm("mov.b64 %0, {%1, %1};" : "=l"(p) : "r"(u));
    return p;
}

// ---------------- global barrier (replay-safe: monotonic counter) ----------------
__device__ __forceinline__ void gbar() {
    __syncthreads();
    if (threadIdx.x == 0) {
        __threadfence();
        unsigned nb = gridDim.x;
        unsigned t = atomicAdd(&d_barc, 1u) + 1u;
        unsigned target = ((t + nb - 1u) / nb) * nb;
        while (*((volatile unsigned*)&d_barc) < target) {}
    }
    __syncthreads();
}

__device__ __forceinline__ int edge_src(const int* ei, int E, int e) {
    return (d_stride == 2) ? ei[2 * e] : ei[e];
}
__device__ __forceinline__ int edge_dst(const int* ei, int E, int e) {
    return (d_stride == 2) ? ei[2 * (E + e)] : ei[E + e];
}

// ---------------- one-shot graph build (persistent, 128 co-resident blocks) ----
__global__ void __launch_bounds__(512, 1)
build_k(const int* __restrict__ ei, int E, int n) {
    __shared__ int sm[512];
    const int G = gridDim.x, Tn = blockDim.x;
    const int NT = G * Tn;
    const int gtid = blockIdx.x * Tn + threadIdx.x;
    const int chunk = (n + G - 1) / G;

    // P0: init deg (self loop), zero stats + tickets, detect edge dtype
    for (int i = gtid; i < n; i += NT) d_deg[i] = 1;
    for (int i = gtid; i < NSTATS * HF; i += NT) {
        ((float*)d_sums)[i] = 0.f;
        ((float*)d_sqs)[i] = 0.f;
    }
    for (int i = gtid; i < NSTATS; i += NT) d_ticket[i] = 0;
    if (blockIdx.x == 0 && threadIdx.x < 32) {
        // int64 little-endian with values < 2^31 -> odd words all zero
        long long total = 2LL * E;
        long long step = total / 33;
        long long pos = ((long long)(threadIdx.x + 1) * step) | 1;
        if (pos >= total) pos = 1;
        unsigned nz = __ballot_sync(0xffffffffu, ei[pos] != 0);
        if (threadIdx.x == 0) d_stride = (nz == 0u) ? 2 : 1;
    }
    gbar();

    // P1: degree count
    for (int e = gtid; e < E; e += NT) atomicAdd(&d_deg[edge_dst(ei, E, e)], 1);
    gbar();

    // P2: dinv
    for (int i = gtid; i < n; i += NT) d_dinv[i] = rsqrtf((float)d_deg[i]);
    gbar();

    // P3: block-local exclusive scan over this block's node chunk
    {
        int cs = blockIdx.x * chunk;
        int ce = min(cs + chunk, n);
        int base = cs + threadIdx.x * 4;
        int vals[4];
        int lsum = 0;
#pragma unroll
        for (int j = 0; j < 4; j++) {
            int idx = base + j;
            int dv = (idx < ce) ? d_deg[idx] : 0;
            vals[j] = dv; lsum += dv;
        }
        sm[threadIdx.x] = lsum;
        __syncthreads();
        for (int d = 1; d < 512; d <<= 1) {
            int t = (threadIdx.x >= d) ? sm[threadIdx.x - d] : 0;
            __syncthreads();
            sm[threadIdx.x] += t;
            __syncthreads();
        }
        int run = sm[threadIdx.x] - lsum;
#pragma unroll
        for (int j = 0; j < 4; j++) {
            int idx = base + j;
            if (idx < ce) { d_offs[idx] = run; run += vals[j]; }
        }
        if (threadIdx.x == Tn - 1) d_part[blockIdx.x] = sm[Tn - 1];
    }
    gbar();

    // P4: block 0 scans the per-block partials (exclusive)
    if (blockIdx.x == 0) {
        int t = threadIdx.x;
        int v = (t < G) ? d_part[t] : 0;
        sm[t] = v;
        __syncthreads();
        for (int d = 1; d < 512; d <<= 1) {
            int u = (t >= d) ? sm[t - d] : 0;
            __syncthreads();
            sm[t] += u;
            __syncthreads();
        }
        if (t < G) d_part[t] = sm[t] - v;
    }
    gbar();

    // P5: finalize offsets, self-loop entries, cursors
    for (int i = gtid; i < n; i += NT) {
        int off = d_offs[i] + d_part[i / chunk];
        d_offs[i] = off;
        float dv = d_dinv[i];
        d_csr2[off] = make_int2(i, __float_as_int(dv * dv));
        d_cursor[i] = off + 1;
    }
    if (gtid == 0) d_offs[n] = n + E;
    gbar();

    // P6: scatter edges
    for (int e = gtid; e < E; e += NT) {
        int s = edge_src(ei, E, e);
        int d = edge_dst(ei, E, e);
        int p = atomicAdd(&d_cursor[d], 1);
        d_csr2[p] = make_int2(s, __float_as_int(d_dinv[s] * d_dinv[d]));
    }
}

// trivial launch to shift the fixed ncu capture slot onto agg128_k
__global__ void shift_k() {
    if (threadIdx.x == 0) d_part[255] = 0;
}

// ---------------- per-layer kernels ----------------
// first layer: d_tmp = x[N,3] @ W0[3,128]   (raw input, no BN)
__global__ void gemm3_k(const float* __restrict__ x, const float* __restrict__ W0,
                        int n) {
    int i = blockIdx.x * blockDim.x + threadIdx.x;
    if (i >= n * 32) return;
    int v = i >> 5;
    int c = (i & 31) << 2;
    float x0 = x[v * 3 + 0], x1 = x[v * 3 + 1], x2 = x[v * 3 + 2];
    float4 w0 = *(const float4*)&W0[c];
    float4 w1 = *(const float4*)&W0[HF + c];
    float4 w2 = *(const float4*)&W0[2 * HF + c];
    float4 o;
    o.x = x0 * w0.x + x1 * w1.x + x2 * w2.x;
    o.y = x0 * w0.y + x1 * w1.y + x2 * w2.y;
    o.z = x0 * w0.z + x1 * w1.z + x2 * w2.z;
    o.w = x0 * w0.w + x1 * w1.w + x2 * w2.w;
    *(float4*)&d_tmp[v * HF + c] = o;
}

// d_tmp[N,128] = (relu(bn_a(A)) [+ relu(bn_b(B))]) @ W[128,128]
// 64x128x32 tile, 256 threads, 4x8 microtile, f32x2 FMA, <=64 regs -> 4 blk/SM.
__global__ void __launch_bounds__(256, 4)
gemm128_k(int aSel, int aStat, int bSel, int bStat,
          const float* __restrict__ W, int n) {
    __shared__ __align__(16) float As[BM][36];   // 144B row stride (16B multiple)
    __shared__ __align__(16) float Ws[BK][HF];
    __shared__ __align__(16) float scA[HF], shA[HF], scB[HF], shB[HF];
    const float* A = sel_buf(aSel);
    const float* B = (bSel >= 0) ? sel_buf(bSel) : (const float*)0;
    int tid = threadIdx.x;
    if (tid < HF) {
        scA[tid] = d_bnsc[aStat][tid];
        shA[tid] = d_bnsh[aStat][tid];
        if (bSel >= 0) { scB[tid] = d_bnsc[bStat][tid]; shB[tid] = d_bnsh[bStat][tid]; }
    }
    int brow = blockIdx.x * BM;
    int r0 = (tid >> 4) << 2;      // 0..60 step 4
    int c0 = (tid & 15) << 3;      // 0..120 step 8
    unsigned long long acc[4][4];
#pragma unroll
    for (int r = 0; r < 4; r++)
#pragma unroll
        for (int j = 0; j < 4; j++) acc[r][j] = 0ULL;

    for (int k0 = 0; k0 < HF; k0 += BK) {
        __syncthreads();    // first iter: covers BN smem; later: end of compute
        // stage A: 64x32 floats = 512 float4 (2/thread), bn+relu(+skip) fused
#pragma unroll
        for (int i = 0; i < 2; i++) {
            int idx = tid + i * 256;
            int ar = idx >> 3, ac = (idx & 7) << 2;
            int grow = brow + ar, f = k0 + ac;
            float4 v = make_float4(0.f, 0.f, 0.f, 0.f);
            if (grow < n) {
                float4 a4 = *(const float4*)&A[(size_t)grow * HF + f];
                float4 sa = *(float4*)&scA[f];
                float4 ha = *(float4*)&shA[f];
                v.x = fmaxf(fmaf(a4.x, sa.x, ha.x), 0.f);
                v.y = fmaxf(fmaf(a4.y, sa.y, ha.y), 0.f);
                v.z = fmaxf(fmaf(a4.z, sa.z, ha.z), 0.f);
                v.w = fmaxf(fmaf(a4.w, sa.w, ha.w), 0.f);
                if (B) {
                    float4 b4 = *(const float4*)&B[(size_t)grow * HF + f];
                    float4 sb = *(float4*)&scB[f];
                    float4 hb = *(float4*)&shB[f];
                    v.x += fmaxf(fmaf(b4.x, sb.x, hb.x), 0.f);
                    v.y += fmaxf(fmaf(b4.y, sb.y, hb.y), 0.f);
                    v.z += fmaxf(fmaf(b4.z, sb.z, hb.z), 0.f);
                    v.w += fmaxf(fmaf(b4.w, sb.w, hb.w), 0.f);
                }
            }
            *(float4*)&As[ar][ac] = v;
        }
        // stage W: 32x128 = 1024 float4 (4/thread)
#pragma unroll
        for (int i = 0; i < 4; i++) {
            int idx = tid + i * 256;
            int kr = idx >> 5, cc = (idx & 31) << 2;
            *(float4*)&Ws[kr][cc] = *(const float4*)&W[(size_t)(k0 + kr) * HF + cc];
        }
        __syncthreads();
#pragma unroll
        for (int kk = 0; kk < BK; kk++) {
            ulonglong2 t0 = *(ulonglong2*)&Ws[kk][c0];
            ulonglong2 t1 = *(ulonglong2*)&Ws[kk][c0 + 4];
            unsigned long long bp0 = t0.x, bp1 = t0.y, bp2 = t1.x, bp3 = t1.y;
#pragma unroll
            for (int r = 0; r < 4; r++) {
                unsigned long long ap = splat2(As[r0 + r][kk]);
                fma2(acc[r][0], ap, bp0);
                fma2(acc[r][1], ap, bp1);
                fma2(acc[r][2], ap, bp2);
                fma2(acc[r][3], ap, bp3);
            }
        }
    }
#pragma unroll
    for (int r = 0; r < 4; r++) {
        int grow = brow + r0 + r;
        if (grow < n) {
            *(ulonglong2*)&d_tmp[(size_t)grow * HF + c0] =
                make_ulonglong2(acc[r][0], acc[r][1]);
            *(ulonglong2*)&d_tmp[(size_t)grow * HF + c0 + 4] =
                make_ulonglong2(acc[r][2], acc[r][3]);
        }
    }
}

// aggregation: sel(dstSel)[v] = sum_{csr} norm * d_tmp[src]; warp/node.
// Unroll-8 with aligned int4 CSR loads for MLP. Fused BN stats + finalize.
__global__ void __launch_bounds__(256, 4)
agg128_k(int n, int dstSel, int statIdx,
         const float* __restrict__ g, const float* __restrict__ b, float invN) {
    float* dst = sel_buf(dstSel);
    const float4* T = (const float4*)d_tmp;
    int gw = (blockIdx.x * blockDim.x + threadIdx.x) >> 5;
    int lane = threadIdx.x & 31;
    int nwarps = (gridDim.x * blockDim.x) >> 5;
    float4 ssum = make_float4(0.f, 0.f, 0.f, 0.f);
    float4 ssq  = make_float4(0.f, 0.f, 0.f, 0.f);
    for (int v = gw; v < n; v += nwarps) {
        int bo = d_offs[v], e = d_offs[v + 1];
        float4 acc = make_float4(0.f, 0.f, 0.f, 0.f);
        int i = bo;
        if ((i & 1) && i < e) {            // align to int4 (2-entry) boundary
            int2 c = d_csr2[i];
            float4 v0 = __ldg(&T[(size_t)c.x * 32 + lane]);
            float nn = __int_as_float(c.y);
            acc.x += nn * v0.x; acc.y += nn * v0.y;
            acc.z += nn * v0.z; acc.w += nn * v0.w;
            i++;
        }
        for (; i + 8 <= e; i += 8) {
            int4 q0 = *(const int4*)&d_csr2[i];
            int4 q1 = *(const int4*)&d_csr2[i + 2];
            int4 q2 = *(const int4*)&d_csr2[i + 4];
            int4 q3 = *(const int4*)&d_csr2[i + 6];
            float4 v0 = __ldg(&T[(size_t)q0.x * 32 + lane]);
            float4 v1 = __ldg(&T[(size_t)q0.z * 32 + lane]);
            float4 v2 = __ldg(&T[(size_t)q1.x * 32 + lane]);
            float4 v3 = __ldg(&T[(size_t)q1.z * 32 + lane]);
            float4 v4 = __ldg(&T[(size_t)q2.x * 32 + lane]);
            float4 v5 = __ldg(&T[(size_t)q2.z * 32 + lane]);
            float4 v6 = __ldg(&T[(size_t)q3.x * 32 + lane]);
            float4 v7 = __ldg(&T[(size_t)q3.z * 32 + lane]);
            float n0 = __int_as_float(q0.y), n1 = __int_as_float(q0.w);
            float n2 = __int_as_float(q1.y), n3 = __int_as_float(q1.w);
            float n4 = __int_as_float(q2.y), n5 = __int_as_float(q2.w);
            float n6 = __int_as_float(q3.y), n7 = __int_as_float(q3.w);
            acc.x += n0*v0.x + n1*v1.x + n2*v2.x + n3*v3.x
                   + n4*v4.x + n5*v5.x + n6*v6.x + n7*v7.x;
            acc.y += n0*v0.y + n1*v1.y + n2*v2.y + n3*v3.y
                   + n4*v4.y + n5*v5.y + n6*v6.y + n7*v7.y;
            acc.z += n0*v0.z + n1*v1.z + n2*v2.z + n3*v3.z
                   + n4*v4.z + n5*v5.z + n6*v6.z + n7*v7.z;
            acc.w += n0*v0.w + n1*v1.w + n2*v2.w + n3*v3.w
                   + n4*v4.w + n5*v5.w + n6*v6.w + n7*v7.w;
        }
        for (; i + 2 <= e; i += 2) {
            int4 q = *(const int4*)&d_csr2[i];
            float4 v0 = __ldg(&T[(size_t)q.x * 32 + lane]);
            float4 v1 = __ldg(&T[(size_t)q.z * 32 + lane]);
            float n0 = __int_as_float(q.y), n1 = __int_as_float(q.w);
            acc.x += n0 * v0.x + n1 * v1.x;
            acc.y += n0 * v0.y + n1 * v1.y;
            acc.z += n0 * v0.z + n1 * v1.z;
            acc.w += n0 * v0.w + n1 * v1.w;
        }
        if (i < e) {
            int2 c = d_csr2[i];
            float4 v0 = __ldg(&T[(size_t)c.x * 32 + lane]);
            float nn = __int_as_float(c.y);
            acc.x += nn * v0.x; acc.y += nn * v0.y;
            acc.z += nn * v0.z; acc.w += nn * v0.w;
        }
        *(float4*)&dst[(size_t)v * HF + lane * 4] = acc;
        ssum.x += acc.x; ssum.y += acc.y; ssum.z += acc.z; ssum.w += acc.w;
        ssq.x += acc.x * acc.x; ssq.y += acc.y * acc.y;
        ssq.z += acc.z * acc.z; ssq.w += acc.w * acc.w;
    }
    int f = lane * 4;
    atomicAdd(&d_sums[statIdx][f + 0], ssum.x);
    atomicAdd(&d_sums[statIdx][f + 1], ssum.y);
    atomicAdd(&d_sums[statIdx][f + 2], ssum.z);
    atomicAdd(&d_sums[statIdx][f + 3], ssum.w);
    atomicAdd(&d_sqs[statIdx][f + 0], ssq.x);
    atomicAdd(&d_sqs[statIdx][f + 1], ssq.y);
    atomicAdd(&d_sqs[statIdx][f + 2], ssq.z);
    atomicAdd(&d_sqs[statIdx][f + 3], ssq.w);

    // last-block BN param finalize.
    // __syncthreads BEFORE the ticket: ALL this block's atomics must be issued
    // before tid0 takes the ticket (R14 bug: missing sync corrupted stats).
    __shared__ int is_last;
    __syncthreads();
    __threadfence();
    if (threadIdx.x == 0) {
        int t = atomicAdd(&d_ticket[statIdx], 1);
        is_last = (t == (int)gridDim.x - 1);
    }
    __syncthreads();
    if (is_last && threadIdx.x < HF) {
        int t0 = threadIdx.x;
        float s_ = *((volatile float*)&d_sums[statIdx][t0]);
        float q_ = *((volatile float*)&d_sqs[statIdx][t0]);
        float m = s_ * invN;
        float v = q_ * invN - m * m;
        float sc = rsqrtf(v + EPS) * g[t0];
        d_bnsc[statIdx][t0] = sc;
        d_bnsh[statIdx][t0] = b[t0] - m * sc;
    }
}

// last layer: t1[v] = dot(relu(bn_h(h[v])) + relu(bn_0(xs0[v])), Wout)
__global__ void dot_out_k(int hSel, int hStat, const float* __restrict__ Wv, int n) {
    int w = (blockIdx.x * blockDim.x + threadIdx.x) >> 5;
    int lane = threadIdx.x & 31;
    if (w >= n) return;
    const float* h = sel_buf(hSel);
    int f = lane * 4;
    float4 a  = *(const float4*)&h[(size_t)w * HF + f];
    float4 b  = *(const float4*)&d_xs[0][(size_t)w * HF + f];
    float4 sh_ = *(float4*)&d_bnsc[hStat][f];
    float4 hh  = *(float4*)&d_bnsh[hStat][f];
    float4 s0  = *(float4*)&d_bnsc[0][f];
    float4 h0  = *(float4*)&d_bnsh[0][f];
    float4 ww = *(const float4*)&Wv[f];
    float sx = fmaxf(fmaf(a.x, sh_.x, hh.x), 0.f) + fmaxf(fmaf(b.x, s0.x, h0.x), 0.f);
    float sy = fmaxf(fmaf(a.y, sh_.y, hh.y), 0.f) + fmaxf(fmaf(b.y, s0.y, h0.y), 0.f);
    float sz = fmaxf(fmaf(a.z, sh_.z, hh.z), 0.f) + fmaxf(fmaf(b.z, s0.z, h0.z), 0.f);
    float sw = fmaxf(fmaf(a.w, sh_.w, hh.w), 0.f) + fmaxf(fmaf(b.w, s0.w, h0.w), 0.f);
    float s = sx * ww.x + sy * ww.y + sz * ww.z + sw * ww.w;
#pragma unroll
    for (int o = 16; o; o >>= 1) s += __shfl_down_sync(0xffffffffu, s, o);
    if (lane == 0) d_t1[w] = s;
}

__global__ void agg_sig_k(float* __restrict__ out, int n) {
    int v = blockIdx.x * blockDim.x + threadIdx.x;
    if (v >= n) return;
    int b = d_offs[v], e = d_offs[v + 1];
    float s = 0.f;
    for (int i = b; i < e; i++)
        s += __int_as_float(d_csr2[i].y) * d_t1[d_csr2[i].x];
    out[v] = 1.0f / (1.0f + expf(-s));
}

// ---------------- launcher (kernel launches ONLY — graph-capture safe) ----------------
extern "C" void kernel_launch(void* const* d_in, const int* in_sizes, int n_in,
                              void* d_out, int out_size) {
    const float* x    = (const float*)d_in[0];
    const int*   ei   = (const int*)d_in[1];     // int32 or int64, device-detected
    const float* W0   = (const float*)d_in[2];
    const float* Ws1  = (const float*)d_in[3];
    const float* g1   = (const float*)d_in[4];
    const float* b1   = (const float*)d_in[5];
    const float* Ws2  = (const float*)d_in[6];
    const float* g2   = (const float*)d_in[7];
    const float* b2   = (const float*)d_in[8];
    const float* Wout = (const float*)d_in[9];
    float* out = (float*)d_out;

    const int N = in_sizes[0] / 3;
    const int E = in_sizes[1] / 2;

    const float invN = 1.0f / (float)N;
    const int TB = 256;
    const int gN    = (N + TB - 1) / TB;
    const int g32   = (N * 32 + TB - 1) / TB;
    const int gGemm = (N + BM - 1) / BM;
    const int gAgg  = 4 * 148;                    // one resident wave

    // --- graph preprocessing: one persistent kernel (software grid barrier) ---
    build_k<<<128, 512>>>(ei, E, N);
    shift_k<<<1, 32>>>();   // shifts ncu capture slot onto agg128_k

    // --- layer 0: conv1[0] -> raw agg in xs[0], stat 0 ---
    gemm3_k<<<g32, TB>>>(x, W0, N);
    agg128_k<<<gAgg, TB>>>(N, 0, 0, g1, b1, invN);
    int cur = 0, curStat = 0;

    // --- up phase: i = 1..9 ---
    for (int i = 1; i <= 9; i++) {
        gemm128_k<<<gGemm, TB>>>(cur, curStat, -1, 0,
                                 Ws1 + (size_t)(i - 1) * HF * HF, N);
        int dst = (i < 9) ? i : 9;               // xs[i] or hA
        agg128_k<<<gAgg, TB>>>(N, dst, i, g1 + (size_t)i * HF, b1 + (size_t)i * HF,
                               invN);
        cur = dst; curStat = i;
    }

    // --- down phase: i = 0..7 (skip-add + both BN+ReLU fused into GEMM) ---
    int h = 9, hStat = 9;
    for (int i = 0; i < 8; i++) {
        int j = 8 - i;                           // xs[j], stat j
        gemm128_k<<<gGemm, TB>>>(h, hStat, j, j,
                                 Ws2 + (size_t)i * HF * HF, N);
        int nh = (h == 9) ? 10 : 9;
        int st = 10 + i;
        agg128_k<<<gAgg, TB>>>(N, nh, st, g2 + (size_t)i * HF, b2 + (size_t)i * HF,
                               invN);
        h = nh; hStat = st;
    }

    // --- final: out = sigmoid(conv(bnrelu(h) + bnrelu(xs0), Wout)) ---
    dot_out_k<<<g32, TB>>>(h, hStat, Wout, N);
    agg_sig_k<<<gN, TB>>>(out, N);
}